// round 13
// baseline (speedup 1.0000x reference)
#include <cuda_runtime.h>
#include <math.h>

#define BB   2048
#define NN   36
#define EMBD 1024
#define SIMD 16
#define HID  32
#define KK   8

// Folded head parameters + handoff flags. All zero-initialized at module
// load; every launch returns them to zero (last finisher resets), so graph
// replays are deterministic.
__device__ float    g_Wc[SIMD * HID];   // Wc[d*32+h]
__device__ float    g_b1[HID];
__device__ float    g_w2[HID];
__device__ int      g_done;
__device__ unsigned g_fin;

__global__ __launch_bounds__(256, 5)
void simgsmn_all(const float* __restrict__ inp1,
                 const float* __restrict__ inp2,
                 const float* __restrict__ gcn_w,
                 const float* __restrict__ out1_v,
                 const float* __restrict__ out1_g,
                 const float* __restrict__ out1_b,
                 const float* __restrict__ out2_v,
                 const float* __restrict__ out2_g,
                 const float* __restrict__ out2_b,
                 float* __restrict__ out) {
    const int tid  = threadIdx.x;
    const int lane = tid & 31;
    const int warp = tid >> 5;

    // ================= CTA 0: fold weights, init out, publish ==============
    if (blockIdx.x == 0) {
        __shared__ float s_wsum[SIMD * HID];
        __shared__ float s_v[HID * 33];      // padded: conflict-free v[h][j]
        __shared__ float s_scale[HID];

        // init out[b] = b2 (atomics accumulate on top)
        const float b2 = out2_b[0];
        #pragma unroll
        for (int m = 0; m < 8; m++)
            out[tid + 256 * m] = b2;

        float ws0 = 0.f, ws1 = 0.f;
        #pragma unroll
        for (int k = 0; k < KK; k++) {
            ws0 += gcn_w[k * (SIMD * HID) + tid];
            ws1 += gcn_w[k * (SIMD * HID) + tid + 256];
        }
        s_wsum[tid]       = ws0;
        s_wsum[tid + 256] = ws1;
        #pragma unroll
        for (int m = 0; m < 4; m++) {
            const int e = tid + 256 * m;
            s_v[(e >> 5) * 33 + (e & 31)] = out1_v[e];
        }
        __syncthreads();

        if (tid < HID) {
            float nrm = 0.f;
            #pragma unroll
            for (int j = 0; j < HID; j++) { float v = s_v[tid * 33 + j]; nrm += v * v; }
            s_scale[tid] = out1_g[tid] / (sqrtf(nrm) + 1e-12f);
            g_b1[tid] = out1_b[tid];

            float n2 = 0.f;
            #pragma unroll
            for (int j = 0; j < HID; j++) { float v = out2_v[j]; n2 += v * v; }
            g_w2[tid] = out2_g[0] * out2_v[tid] / (sqrtf(n2) + 1e-12f);
        }
        __syncthreads();

        #pragma unroll
        for (int m = 0; m < 2; m++) {
            const int e  = tid + 256 * m;
            const int dd = e >> 5, h = e & 31;
            float acc = 0.f;
            #pragma unroll
            for (int j = 0; j < HID; j++)
                acc += s_wsum[dd * HID + j] * s_v[h * 33 + j];
            g_Wc[e] = acc * s_scale[h];
        }
        __syncthreads();
        if (tid == 0) {
            __threadfence();             // publish g_* and out[] device-wide
            atomicExch(&g_done, 1);
        }
        return;
    }

    // ================= streaming CTAs =================
    const int blk = blockIdx.x - 1;      // 0 .. BB*9-1
    const int b   = blk / 9;
    const int p   = blk - b * 9;

    __shared__ float s_sim[4][SIMD];

    // ---- streaming: 4 rows, 8 front-batched LDG.128 per thread ----
    const int rg  = tid >> 6;            // row within the 4-row pass
    const int rr  = tid & 63;
    const int d   = rr >> 2;             // sim block 0..15
    const int u   = rr & 3;              // quarter within block

    const int i    = p * 4 + rg;         // row 0..35
    const int boff = d * 64 + u * 4;
    const size_t base = (size_t)b * (NN * EMBD) + (size_t)i * EMBD + boff;

    const float4* qp = reinterpret_cast<const float4*>(inp1 + base);
    const float4* cp = reinterpret_cast<const float4*>(inp2 + base);

    float4 q0 = __ldcs(qp + 0);
    float4 q1 = __ldcs(qp + 4);
    float4 q2 = __ldcs(qp + 8);
    float4 q3 = __ldcs(qp + 12);
    float4 c0 = __ldcs(cp + 0);
    float4 c1 = __ldcs(cp + 4);
    float4 c2 = __ldcs(cp + 8);
    float4 c3 = __ldcs(cp + 12);

    float dqc = q0.x * c0.x + q0.y * c0.y + q0.z * c0.z + q0.w * c0.w
              + q1.x * c1.x + q1.y * c1.y + q1.z * c1.z + q1.w * c1.w
              + q2.x * c2.x + q2.y * c2.y + q2.z * c2.z + q2.w * c2.w
              + q3.x * c3.x + q3.y * c3.y + q3.z * c3.z + q3.w * c3.w;
    float nq  = q0.x * q0.x + q0.y * q0.y + q0.z * q0.z + q0.w * q0.w
              + q1.x * q1.x + q1.y * q1.y + q1.z * q1.z + q1.w * q1.w
              + q2.x * q2.x + q2.y * q2.y + q2.z * q2.z + q2.w * q2.w
              + q3.x * q3.x + q3.y * q3.y + q3.z * q3.z + q3.w * q3.w;
    float nc  = c0.x * c0.x + c0.y * c0.y + c0.z * c0.z + c0.w * c0.w
              + c1.x * c1.x + c1.y * c1.y + c1.z * c1.z + c1.w * c1.w
              + c2.x * c2.x + c2.y * c2.y + c2.z * c2.z + c2.w * c2.w
              + c3.x * c3.x + c3.y * c3.y + c3.z * c3.z + c3.w * c3.w;

    #pragma unroll
    for (int o = 2; o > 0; o >>= 1) {
        dqc += __shfl_xor_sync(0xFFFFFFFFu, dqc, o);
        nq  += __shfl_xor_sync(0xFFFFFFFFu, nq,  o);
        nc  += __shfl_xor_sync(0xFFFFFFFFu, nc,  o);
    }
    if (u == 0)
        s_sim[rg][d] = dqc * rsqrtf(nq * nc);

    // ---- producer/consumer handoff: warps 1-7 arrive & retire ----
    if (warp != 0) {
        asm volatile("bar.arrive 1, 256;" ::: "memory");
        return;
    }
    asm volatile("bar.sync 1, 256;" ::: "memory");   // smem release-acquire

    // ---- wait for fold publication (normally already done) ----
    {
        int done;
        do {
            asm volatile("ld.global.acquire.gpu.b32 %0, [%1];"
                         : "=r"(done) : "l"(&g_done));
            if (!done) __nanosleep(64);
        } while (!done);
    }

    // ---- load folded weights: 18 coalesced L2-hit loads per warp ----
    float wc[SIMD];
    #pragma unroll
    for (int dd = 0; dd < SIMD; dd++)
        wc[dd] = g_Wc[dd * HID + lane];          // 128B line per LDG
    const float b1 = g_b1[lane];
    const float w2 = g_w2[lane];

    // ---- head: warp 0 scores all 4 rows; lane = hidden unit h ----
    float rowsum = 0.f;
    #pragma unroll
    for (int r = 0; r < 4; r++) {
        float acc = b1;
        #pragma unroll
        for (int dd = 0; dd < SIMD; dd++)
            acc += s_sim[r][dd] * wc[dd];
        rowsum += tanhf(acc) * w2;
    }
    #pragma unroll
    for (int o = 16; o > 0; o >>= 1)
        rowsum += __shfl_xor_sync(0xFFFFFFFFu, rowsum, o);

    if (lane == 0) {
        atomicAdd(&out[b], rowsum * (1.0f / NN));
        // completion count; last streaming CTA resets flags for next replay
        unsigned v = atomicAdd(&g_fin, 1);
        if (v == (unsigned)(BB * 9 - 1)) {
            g_fin  = 0;
            g_done = 0;
        }
    }
}

extern "C" void kernel_launch(void* const* d_in, const int* in_sizes, int n_in,
                              void* d_out, int out_size) {
    const float* inp1   = (const float*)d_in[0];
    const float* inp2   = (const float*)d_in[1];
    // d_in[2]=gk_mean, d_in[3]=gk_prec: unused — Gaussian branch collapses to
    // sum_j w_norm = S/(S+1e-8) = 1 - O(1e-7), below output tolerance.
    const float* gcn_w  = (const float*)d_in[4];
    const float* out1_v = (const float*)d_in[5];
    const float* out1_g = (const float*)d_in[6];
    const float* out1_b = (const float*)d_in[7];
    const float* out2_v = (const float*)d_in[8];
    const float* out2_g = (const float*)d_in[9];
    const float* out2_b = (const float*)d_in[10];
    float* out = (float*)d_out;

    simgsmn_all<<<BB * 9 + 1, 256>>>(inp1, inp2, gcn_w, out1_v, out1_g, out1_b,
                                     out2_v, out2_g, out2_b, out);
}

// round 14
// speedup vs baseline: 1.1021x; 1.1021x over previous
#include <cuda_runtime.h>
#include <math.h>

#define BB   2048
#define NN   36
#define EMBD 1024
#define SIMD 16
#define HID  32
#define KK   8

// Folded head parameters (written by fold_kernel each launch — deterministic).
__device__ float g_Wc[SIMD * HID];   // Wc[d*32+h]
__device__ float g_b1[HID];
__device__ float g_w2[HID];

__device__ __forceinline__ unsigned smem_u32(const void* p) {
    return (unsigned)__cvta_generic_to_shared(p);
}
__device__ __forceinline__ void cp_async16(unsigned dst, const void* src) {
    asm volatile("cp.async.ca.shared.global [%0], [%1], 16;" :: "r"(dst), "l"(src));
}

// ---- kernel 1: fold weights (CTA 0) + init out[b] = b2 (all CTAs) ----
// Triggers programmatic launch completion at entry so the streaming kernel
// overlaps this one; consumers gate on cudaGridDependencySynchronize().
__global__ __launch_bounds__(256)
void fold_kernel(const float* __restrict__ gcn_w,
                 const float* __restrict__ out1_v,
                 const float* __restrict__ out1_g,
                 const float* __restrict__ out1_b,
                 const float* __restrict__ out2_v,
                 const float* __restrict__ out2_g,
                 const float* __restrict__ out2_b,
                 float* __restrict__ out) {
    cudaTriggerProgrammaticLaunchCompletion();

    const int tid = threadIdx.x;

    // every CTA: init 256 outputs to b2 (atomics accumulate on top)
    out[blockIdx.x * 256 + tid] = out2_b[0];

    if (blockIdx.x != 0) return;

    __shared__ float s_wsum[SIMD * HID];
    __shared__ float s_v[HID * 33];       // padded: conflict-free v[h][j]
    __shared__ float s_scale[HID];

    float ws0 = 0.f, ws1 = 0.f;
    #pragma unroll
    for (int k = 0; k < KK; k++) {
        ws0 += gcn_w[k * (SIMD * HID) + tid];
        ws1 += gcn_w[k * (SIMD * HID) + tid + 256];
    }
    s_wsum[tid]       = ws0;
    s_wsum[tid + 256] = ws1;
    #pragma unroll
    for (int m = 0; m < 4; m++) {
        const int e = tid + 256 * m;
        s_v[(e >> 5) * 33 + (e & 31)] = out1_v[e];
    }
    __syncthreads();

    if (tid < HID) {
        float nrm = 0.f;
        #pragma unroll
        for (int j = 0; j < HID; j++) { float v = s_v[tid * 33 + j]; nrm += v * v; }
        s_scale[tid] = out1_g[tid] / (sqrtf(nrm) + 1e-12f);
        g_b1[tid] = out1_b[tid];

        float n2 = 0.f;
        #pragma unroll
        for (int j = 0; j < HID; j++) { float v = out2_v[j]; n2 += v * v; }
        g_w2[tid] = out2_g[0] * out2_v[tid] / (sqrtf(n2) + 1e-12f);
    }
    __syncthreads();

    #pragma unroll
    for (int m = 0; m < 2; m++) {
        const int e  = tid + 256 * m;
        const int dd = e >> 5, h = e & 31;
        float acc = 0.f;
        #pragma unroll
        for (int j = 0; j < HID; j++)
            acc += s_wsum[dd * HID + j] * s_v[h * 33 + j];
        g_Wc[e] = acc * s_scale[h];
    }
}

// ---- kernel 2: streaming cosine-sim + warp-0 head + one atomic ----
__global__ __launch_bounds__(256, 5)
void sim_head_kernel(const float* __restrict__ inp1,
                     const float* __restrict__ inp2,
                     float* __restrict__ out) {
    const int blk = blockIdx.x;          // 0 .. BB*9-1
    const int b   = blk / 9;
    const int p   = blk - b * 9;

    const int tid  = threadIdx.x;
    const int lane = tid & 31;
    const int warp = tid >> 5;

    __shared__ float s_wc[SIMD * HID];   // 2 KB
    __shared__ float s_b1[HID];
    __shared__ float s_w2[HID];
    __shared__ float s_sim[4][SIMD];

    // ---- streaming: 4 rows, 8 front-batched LDG.128 per thread ----
    const int rg  = tid >> 6;            // row within the 4-row pass
    const int rr  = tid & 63;
    const int d   = rr >> 2;             // sim block 0..15
    const int u   = rr & 3;              // quarter within block

    const int i    = p * 4 + rg;         // row 0..35
    const int boff = d * 64 + u * 4;
    const size_t base = (size_t)b * (NN * EMBD) + (size_t)i * EMBD + boff;

    const float4* qp = reinterpret_cast<const float4*>(inp1 + base);
    const float4* cp = reinterpret_cast<const float4*>(inp2 + base);

    float4 q0 = __ldcs(qp + 0);
    float4 q1 = __ldcs(qp + 4);
    float4 q2 = __ldcs(qp + 8);
    float4 q3 = __ldcs(qp + 12);
    float4 c0 = __ldcs(cp + 0);
    float4 c1 = __ldcs(cp + 4);
    float4 c2 = __ldcs(cp + 8);
    float4 c3 = __ldcs(cp + 12);

    // warp 0: gate on fold completion (loads above already in flight), then
    // prefetch folded weights. Waves >= 2 see the sync as a no-op.
    if (warp == 0) {
        cudaGridDependencySynchronize();
        #pragma unroll
        for (int m = 0; m < 4; m++)
            cp_async16(smem_u32(&s_wc[(lane + 32 * m) * 4]), &g_Wc[(lane + 32 * m) * 4]);
        if (lane < 8)
            cp_async16(smem_u32(&s_b1[lane * 4]), &g_b1[lane * 4]);
        else if (lane < 16)
            cp_async16(smem_u32(&s_w2[(lane - 8) * 4]), &g_w2[(lane - 8) * 4]);
        asm volatile("cp.async.commit_group;");
    }

    float dqc = q0.x * c0.x + q0.y * c0.y + q0.z * c0.z + q0.w * c0.w
              + q1.x * c1.x + q1.y * c1.y + q1.z * c1.z + q1.w * c1.w
              + q2.x * c2.x + q2.y * c2.y + q2.z * c2.z + q2.w * c2.w
              + q3.x * c3.x + q3.y * c3.y + q3.z * c3.z + q3.w * c3.w;
    float nq  = q0.x * q0.x + q0.y * q0.y + q0.z * q0.z + q0.w * q0.w
              + q1.x * q1.x + q1.y * q1.y + q1.z * q1.z + q1.w * q1.w
              + q2.x * q2.x + q2.y * q2.y + q2.z * q2.z + q2.w * q2.w
              + q3.x * q3.x + q3.y * q3.y + q3.z * q3.z + q3.w * q3.w;
    float nc  = c0.x * c0.x + c0.y * c0.y + c0.z * c0.z + c0.w * c0.w
              + c1.x * c1.x + c1.y * c1.y + c1.z * c1.z + c1.w * c1.w
              + c2.x * c2.x + c2.y * c2.y + c2.z * c2.z + c2.w * c2.w
              + c3.x * c3.x + c3.y * c3.y + c3.z * c3.z + c3.w * c3.w;

    #pragma unroll
    for (int o = 2; o > 0; o >>= 1) {
        dqc += __shfl_xor_sync(0xFFFFFFFFu, dqc, o);
        nq  += __shfl_xor_sync(0xFFFFFFFFu, nq,  o);
        nc  += __shfl_xor_sync(0xFFFFFFFFu, nc,  o);
    }
    if (u == 0)
        s_sim[rg][d] = dqc * rsqrtf(nq * nc);

    // ---- producer/consumer handoff: warps 1-7 arrive & retire ----
    if (warp != 0) {
        asm volatile("bar.arrive 1, 256;" ::: "memory");
        return;
    }

    asm volatile("cp.async.wait_group 0;");
    asm volatile("bar.sync 1, 256;" ::: "memory");   // smem release-acquire

    // ---- head: warp 0 scores all 4 rows; lane = hidden unit h ----
    float rowsum = 0.f;
    #pragma unroll
    for (int r = 0; r < 4; r++) {
        float acc = s_b1[lane];
        #pragma unroll
        for (int dd = 0; dd < SIMD; dd++)
            acc += s_sim[r][dd] * s_wc[dd * HID + lane];
        rowsum += tanhf(acc) * s_w2[lane];
    }
    #pragma unroll
    for (int o = 16; o > 0; o >>= 1)
        rowsum += __shfl_xor_sync(0xFFFFFFFFu, rowsum, o);

    if (lane == 0)
        atomicAdd(&out[b], rowsum * (1.0f / NN));
}

extern "C" void kernel_launch(void* const* d_in, const int* in_sizes, int n_in,
                              void* d_out, int out_size) {
    const float* inp1   = (const float*)d_in[0];
    const float* inp2   = (const float*)d_in[1];
    // d_in[2]=gk_mean, d_in[3]=gk_prec: unused — Gaussian branch collapses to
    // sum_j w_norm = S/(S+1e-8) = 1 - O(1e-7), below output tolerance.
    const float* gcn_w  = (const float*)d_in[4];
    const float* out1_v = (const float*)d_in[5];
    const float* out1_g = (const float*)d_in[6];
    const float* out1_b = (const float*)d_in[7];
    const float* out2_v = (const float*)d_in[8];
    const float* out2_g = (const float*)d_in[9];
    const float* out2_b = (const float*)d_in[10];
    float* out = (float*)d_out;

    fold_kernel<<<BB / 256, 256>>>(gcn_w, out1_v, out1_g, out1_b,
                                   out2_v, out2_g, out2_b, out);

    // main kernel with programmatic dependent launch: overlaps the fold;
    // warp 0 gates on cudaGridDependencySynchronize() before consuming.
    {
        cudaLaunchConfig_t cfg = {};
        cfg.gridDim  = dim3(BB * 9, 1, 1);
        cfg.blockDim = dim3(256, 1, 1);
        cfg.dynamicSmemBytes = 0;
        cfg.stream = 0;
        cudaLaunchAttribute attr[1];
        attr[0].id = cudaLaunchAttributeProgrammaticStreamSerialization;
        attr[0].val.programmaticStreamSerializationAllowed = 1;
        cfg.attrs = attr;
        cfg.numAttrs = 1;
        cudaLaunchKernelEx(&cfg, sim_head_kernel, inp1, inp2, (float*)d_out);
    }
}